// round 12
// baseline (speedup 1.0000x reference)
#include <cuda_runtime.h>
#include <math.h>
#include <cstdint>

// Problem constants
#define Bn 2
#define Tn 2048
#define Cn 1024
#define Hn 16
#define Dn 64
#define Mrows (Bn * Tn)   // 4096

// Scratch (allocation-free), all [B*T, C] row-major
__device__ float g_q[(size_t)Mrows * Cn];
__device__ float g_k[(size_t)Mrows * Cn];
__device__ float g_v[(size_t)Mrows * Cn];
__device__ float g_y[(size_t)Mrows * Cn];
__device__ float g_xr[(size_t)Mrows * Cn];        // tf32-rounded x
__device__ float g_wr[4][(size_t)Cn * Cn];        // tf32-rounded Wq,Wk,Wv,Wo

// ---------------------------------------------------------------------------
// Helpers
// ---------------------------------------------------------------------------
__device__ __forceinline__ float cvt_tf32(float x) {
    float r;
    asm("cvt.rna.tf32.f32 %0, %1;" : "=f"(r) : "f"(x));
    return r;
}
__device__ __forceinline__ uint32_t smem_u32(const void* p) {
    uint32_t a;
    asm("{ .reg .u64 t; cvta.to.shared.u64 t, %1; cvt.u32.u64 %0, t; }" : "=r"(a) : "l"(p));
    return a;
}
__device__ __forceinline__ void cp16(uint32_t dst, const void* src) {
    asm volatile("cp.async.cg.shared.global [%0], [%1], 16;" :: "r"(dst), "l"(src));
}
#define CP_COMMIT() asm volatile("cp.async.commit_group;" ::: "memory")
#define CP_WAIT1()  asm volatile("cp.async.wait_group 1;" ::: "memory")

// D(16x8) += A(16x8) * B(8x8); A row-major frag (4 regs), B col-major frag (2 regs)
__device__ __forceinline__ void mma_tf32(float* d, float a0, float a1, float a2, float a3,
                                         float b0, float b1) {
    asm volatile(
        "mma.sync.aligned.m16n8k8.row.col.f32.tf32.tf32.f32 "
        "{%0,%1,%2,%3}, {%4,%5,%6,%7}, {%8,%9}, {%0,%1,%2,%3};"
        : "+f"(d[0]), "+f"(d[1]), "+f"(d[2]), "+f"(d[3])
        : "r"(__float_as_uint(a0)), "r"(__float_as_uint(a1)),
          "r"(__float_as_uint(a2)), "r"(__float_as_uint(a3)),
          "r"(__float_as_uint(b0)), "r"(__float_as_uint(b1)));
}

// ---------------------------------------------------------------------------
// Prep: round x and the four weight matrices to tf32 (enables raw cp.async)
// ---------------------------------------------------------------------------
__global__ void prep_round(const float* __restrict__ x,
                           const float* __restrict__ wq, const float* __restrict__ wk,
                           const float* __restrict__ wv, const float* __restrict__ wo)
{
    const int seg = blockIdx.y;
    const float* src;
    float* dst;
    int n4;
    if (seg == 0) { src = x;  dst = g_xr;    n4 = Mrows * Cn / 4; }
    else {
        src = (seg == 1) ? wq : (seg == 2) ? wk : (seg == 3) ? wv : wo;
        dst = g_wr[seg - 1];
        n4 = Cn * Cn / 4;
    }
    const int i = blockIdx.x * blockDim.x + threadIdx.x;
    if (i < n4) {
        float4 v = ((const float4*)src)[i];
        v.x = cvt_tf32(v.x); v.y = cvt_tf32(v.y);
        v.z = cvt_tf32(v.z); v.w = cvt_tf32(v.w);
        ((float4*)dst)[i] = v;
    }
}

// ---------------------------------------------------------------------------
// GEMM: C[M,N] = A[M,K] @ W[N,K]^T (tf32 mma.sync, fp32 accum).
// CTA 128x128, BK=32, 3-stage cp.async pipeline, 8 warps (4m x 2n), 32x64 warp tile.
// Smem per stage per matrix: [128 rows][32 floats], 16B chunk c at (c ^ (r&7)).
// __launch_bounds__(256,2): 2 CTAs/SM (96KB x 2 = 192KB smem, <=128 regs).
// RoPE fused for q,k; tf32 rounding on q,k,v outputs (do_rope launch).
// ---------------------------------------------------------------------------
#define GEMM_SMEM_BYTES 98304   // 2 matrices x 3 stages x 16384 B

__global__ __launch_bounds__(256, 2) void gemm_mma(
    const float* __restrict__ A,
    const float* __restrict__ W0, const float* __restrict__ W1, const float* __restrict__ W2,
    float* __restrict__ C0, float* __restrict__ C1, float* __restrict__ C2,
    int do_rope)
{
    extern __shared__ float sm[];
    float* smA = sm;                 // 3 x 4096 floats
    float* smB = sm + 3 * 4096;
    const uint32_t smbA = smem_u32(smA);
    const uint32_t smbB = smem_u32(smB);

    const int z = blockIdx.z;
    const float* W = (z == 0) ? W0 : ((z == 1) ? W1 : W2);
    float*      Cm = (z == 0) ? C0 : ((z == 1) ? C1 : C2);
    const bool rope = (do_rope != 0) && (z < 2);
    const bool rnd  = (do_rope != 0);

    const int tid = threadIdx.x;
    const int wid = tid >> 5, lane = tid & 31;
    const int warpM = wid >> 1, warpN = wid & 1;
    const int lq = lane >> 2, lr4 = lane & 3;
    const int rowBase = blockIdx.y * 128;
    const int colBase = blockIdx.x * 128;

    // cp.async mapping: row cr (0..127), k-half (16 floats); 4 16B chunks per matrix
    const int cr = tid >> 1, half = tid & 1;
    const float* Ag = A + (size_t)(rowBase + cr) * Cn + half * 16;
    const float* Wg = W + (size_t)(colBase + cr) * Cn + half * 16;
    uint32_t dOf[4];
#pragma unroll
    for (int i = 0; i < 4; i++) {
        const int chunk = half * 4 + i;
        dOf[i] = (uint32_t)((cr * 32 + ((chunk ^ (cr & 7)) << 2)) * 4);
    }

#define G_ISSUE(t, s) do {                                            \
        const float* _ga = Ag + (t) * 32;                             \
        const float* _gw = Wg + (t) * 32;                             \
        const uint32_t _ba = smbA + (s) * 16384;                      \
        const uint32_t _bb = smbB + (s) * 16384;                      \
        _Pragma("unroll")                                             \
        for (int _i = 0; _i < 4; _i++) {                              \
            cp16(_ba + dOf[_i], _ga + _i * 4);                        \
            cp16(_bb + dOf[_i], _gw + _i * 4);                        \
        }                                                             \
    } while (0)

    G_ISSUE(0, 0); CP_COMMIT();
    G_ISSUE(1, 1); CP_COMMIT();

    float acc[2][8][4];
#pragma unroll
    for (int i = 0; i < 2; i++)
#pragma unroll
        for (int j = 0; j < 8; j++)
#pragma unroll
            for (int k = 0; k < 4; k++) acc[i][j][k] = 0.f;

#pragma unroll 1
    for (int t = 0; t < 32; t++) {
        CP_WAIT1();
        __syncthreads();
        if (t + 2 < 32) G_ISSUE(t + 2, (t + 2) % 3);
        CP_COMMIT();

        const float* sA = smA + (t % 3) * 4096;
        const float* sB = smB + (t % 3) * 4096;
#pragma unroll
        for (int ks = 0; ks < 4; ks++) {
            const int c0 = ((ks * 2 + 0) ^ lq) << 2;
            const int c1 = ((ks * 2 + 1) ^ lq) << 2;
            float a[2][4];
#pragma unroll
            for (int mf = 0; mf < 2; mf++) {
                const int r1 = warpM * 32 + mf * 16 + lq;
                const int r2 = r1 + 8;
                a[mf][0] = sA[r1 * 32 + c0 + lr4];
                a[mf][1] = sA[r2 * 32 + c0 + lr4];
                a[mf][2] = sA[r1 * 32 + c1 + lr4];
                a[mf][3] = sA[r2 * 32 + c1 + lr4];
            }
#pragma unroll
            for (int nf = 0; nf < 8; nf++) {
                const int rn = warpN * 64 + nf * 8 + lq;
                const float b0 = sB[rn * 32 + c0 + lr4];
                const float b1 = sB[rn * 32 + c1 + lr4];
#pragma unroll
                for (int mf = 0; mf < 2; mf++)
                    mma_tf32(acc[mf][nf], a[mf][0], a[mf][1], a[mf][2], a[mf][3], b0, b1);
            }
        }
    }

    // Epilogue
    const float KLOG = 13.287712379549449f / 32.0f;   // log2(10000)/32
#pragma unroll
    for (int mf = 0; mf < 2; mf++) {
        const int r0 = rowBase + warpM * 32 + mf * 16 + lq;
        if (!rope) {
#pragma unroll
            for (int nf = 0; nf < 8; nf++) {
                const int c0 = colBase + warpN * 64 + nf * 8 + 2 * lr4;
                float v0 = acc[mf][nf][0], v1 = acc[mf][nf][1];
                float v2 = acc[mf][nf][2], v3 = acc[mf][nf][3];
                if (rnd) { v0 = cvt_tf32(v0); v1 = cvt_tf32(v1);
                           v2 = cvt_tf32(v2); v3 = cvt_tf32(v3); }
                *(float2*)&Cm[(size_t)r0 * Cn + c0]       = make_float2(v0, v1);
                *(float2*)&Cm[(size_t)(r0 + 8) * Cn + c0] = make_float2(v2, v3);
            }
        } else {
            const int t0 = r0 & (Tn - 1), t1 = (r0 + 8) & (Tn - 1);
#pragma unroll
            for (int nf = 0; nf < 4; nf++) {       // d in [0,32): partner frag nf+4
                const int dlo = nf * 8 + 2 * lr4;
                const int c0 = colBase + warpN * 64 + dlo;
#pragma unroll
                for (int e = 0; e < 2; e++) {
                    const float freq = exp2f(-(float)(dlo + e) * KLOG);
                    float s0, cth0, s1, cth1;
                    sincosf((float)t0 * freq, &s0, &cth0);
                    sincosf((float)t1 * freq, &s1, &cth1);
                    const float lo0 = acc[mf][nf][e],     hi0 = acc[mf][nf + 4][e];
                    const float lo1 = acc[mf][nf][e + 2], hi1 = acc[mf][nf + 4][e + 2];
                    Cm[(size_t)r0 * Cn + c0 + e]            = cvt_tf32(lo0 * cth0 - hi0 * s0);
                    Cm[(size_t)r0 * Cn + c0 + e + 32]       = cvt_tf32(hi0 * cth0 + lo0 * s0);
                    Cm[(size_t)(r0 + 8) * Cn + c0 + e]      = cvt_tf32(lo1 * cth1 - hi1 * s1);
                    Cm[(size_t)(r0 + 8) * Cn + c0 + e + 32] = cvt_tf32(hi1 * cth1 + lo1 * s1);
                }
            }
        }
    }
#undef G_ISSUE
}

// ---------------------------------------------------------------------------
// Flash attention, tf32 mma.sync, q-tile=64, k-tile=64, 2-stage cp.async K/V.
// 256 threads, 8 warps (4m x 2n), warp tile 16x32. 2 CTAs/SM (100KB smem).
// Softmax: 4 threads/row, quad-shfl reductions.
// Smem floats: Q 4096 | K 2x4096 | V 2x4096 | P 64x68 | stats 192 = 25024.
// ---------------------------------------------------------------------------
#define AQ 0
#define AK 4096
#define AV 12288
#define AP 20480
#define AM 24832
#define AL 24896
#define AA 24960
#define ATTN_SMEM_FLOATS 25024
#define PSm(m, c) sm[AP + (m) * 68 + (c)]

__global__ __launch_bounds__(256, 2) void attn_kernel(
    const float* __restrict__ Qg, const float* __restrict__ Kg,
    const float* __restrict__ Vg, float* __restrict__ Yg)
{
    extern __shared__ float sm[];
    const uint32_t smb = smem_u32(sm);
    const int qi = (int)(gridDim.x - 1 - blockIdx.x);   // long tiles first
    const int h = blockIdx.y, b = blockIdx.z;
    const int tid = threadIdx.x;
    const int wid = tid >> 5, lane = tid & 31;
    const int wM = wid >> 1, wN = wid & 1;
    const int lq = lane >> 2, lr4 = lane & 3;
    const int m0 = wM * 16, n0 = wN * 32;

    // cp.async mapping: 64 rows x 16 chunks(16B) per tile; 4 chunks per thread
    const int qr = tid >> 2, qc = tid & 3;
    const float* Qp = Qg + (size_t)(b * Tn + qi * 64 + qr) * Cn + h * 64 + qc * 16;
    const float* Kp = Kg + (size_t)(b * Tn + qr) * Cn + h * 64 + qc * 16;
    const float* Vp = Vg + (size_t)(b * Tn + qr) * Cn + h * 64 + qc * 16;
    uint32_t dOf[4];
#pragma unroll
    for (int i = 0; i < 4; i++) {
        const int chunk = qc * 4 + i;
        dOf[i] = (uint32_t)((qr * 64 + ((chunk ^ (qr & 7)) << 2)) * 4);
    }

#define KV_ISSUE(j, s) do {                                                     \
        const float* _kp = Kp + (size_t)((j) * 64) * Cn;                        \
        const float* _vp = Vp + (size_t)((j) * 64) * Cn;                        \
        const uint32_t _bk = smb + (uint32_t)((AK + (s) * 4096) * 4);           \
        const uint32_t _bv = smb + (uint32_t)((AV + (s) * 4096) * 4);           \
        _Pragma("unroll")                                                       \
        for (int _i = 0; _i < 4; _i++) {                                        \
            cp16(_bk + dOf[_i], _kp + _i * 4);                                  \
            cp16(_bv + dOf[_i], _vp + _i * 4);                                  \
        }                                                                       \
    } while (0)

    // Prologue: group0 = Q + KV(0); group1 = KV(1)
#pragma unroll
    for (int i = 0; i < 4; i++) cp16(smb + dOf[i], Qp + i * 4);
    KV_ISSUE(0, 0); CP_COMMIT();
    KV_ISSUE(1, 1); CP_COMMIT();

    if (tid < 64) { sm[AM + tid] = -1e30f; sm[AL + tid] = 0.f; }

    float o[4][4];
#pragma unroll
    for (int j = 0; j < 4; j++)
#pragma unroll
        for (int k = 0; k < 4; k++) o[j][k] = 0.f;

    const int jmax = qi + 1;
#pragma unroll 1
    for (int j = 0; j < jmax; j++) {
        CP_WAIT1();
        __syncthreads();

        const float* sQ = sm + AQ;
        const float* sK = sm + AK + (j & 1) * 4096;
        const float* sV = sm + AV + (j & 1) * 4096;

        // ---- S = Q K^T (warp tile 16x32) ----
        float s[4][4];
#pragma unroll
        for (int jj = 0; jj < 4; jj++)
#pragma unroll
            for (int k = 0; k < 4; k++) s[jj][k] = 0.f;
#pragma unroll
        for (int kd = 0; kd < 8; kd++) {
            const int c0 = ((kd * 2 + 0) ^ lq) << 2;
            const int c1 = ((kd * 2 + 1) ^ lq) << 2;
            const int r1 = m0 + lq, r2 = r1 + 8;
            const float a0 = sQ[r1 * 64 + c0 + lr4];
            const float a1 = sQ[r2 * 64 + c0 + lr4];
            const float a2 = sQ[r1 * 64 + c1 + lr4];
            const float a3 = sQ[r2 * 64 + c1 + lr4];
#pragma unroll
            for (int nf = 0; nf < 4; nf++) {
                const int rn = n0 + nf * 8 + lq;
                const float b0 = sK[rn * 64 + c0 + lr4];
                const float b1 = sK[rn * 64 + c1 + lr4];
                mma_tf32(s[nf], a0, a1, a2, a3, b0, b1);
            }
        }

        // ---- scale + mask + store S to P ----
        const bool need_mask = (j == qi);
        {
            const int r0 = m0 + lq;
#pragma unroll
            for (int nf = 0; nf < 4; nf++) {
                const int c0 = n0 + nf * 8 + 2 * lr4;
                float v0 = s[nf][0] * 0.125f, v1 = s[nf][1] * 0.125f;
                float v2 = s[nf][2] * 0.125f, v3 = s[nf][3] * 0.125f;
                if (need_mask) {
                    const int mg0 = qi * 64 + r0, mg1 = mg0 + 8;
                    const int cg0 = j * 64 + c0, cg1 = cg0 + 1;
                    if (cg0 > mg0) v0 = -1e30f;
                    if (cg1 > mg0) v1 = -1e30f;
                    if (cg0 > mg1) v2 = -1e30f;
                    if (cg1 > mg1) v3 = -1e30f;
                }
                *(float2*)&PSm(r0, c0)     = make_float2(v0, v1);
                *(float2*)&PSm(r0 + 8, c0) = make_float2(v2, v3);
            }
        }
        __syncthreads();

        // ---- online softmax: 4 threads per row, quad shfl reduce ----
        {
            const int r = tid >> 2;
            const int ch = (tid & 3) * 16;
            const float m_old = sm[AM + r];
            float mx = m_old;
#pragma unroll
            for (int c = 0; c < 16; c++) mx = fmaxf(mx, PSm(r, ch + c));
            mx = fmaxf(mx, __shfl_xor_sync(0xffffffffu, mx, 1));
            mx = fmaxf(mx, __shfl_xor_sync(0xffffffffu, mx, 2));
            const float alpha = __expf(m_old - mx);
            float ssum = 0.f;
#pragma unroll
            for (int c = 0; c < 16; c++) {
                float p = __expf(PSm(r, ch + c) - mx);
                PSm(r, ch + c) = cvt_tf32(p);
                ssum += p;
            }
            ssum += __shfl_xor_sync(0xffffffffu, ssum, 1);
            ssum += __shfl_xor_sync(0xffffffffu, ssum, 2);
            if ((tid & 3) == 0) {
                sm[AM + r] = mx;
                sm[AA + r] = alpha;
                sm[AL + r] = sm[AL + r] * alpha + ssum;
            }
        }
        __syncthreads();

        // ---- O = O*alpha + P V ----
        const float al0 = sm[AA + m0 + lq];
        const float al1 = sm[AA + m0 + lq + 8];
#pragma unroll
        for (int nf = 0; nf < 4; nf++) {
            o[nf][0] *= al0; o[nf][1] *= al0;
            o[nf][2] *= al1; o[nf][3] *= al1;
        }
#pragma unroll
        for (int kc = 0; kc < 8; kc++) {
            const int k0 = kc * 8;
            const int r1 = m0 + lq, r2 = r1 + 8;
            const float a0 = PSm(r1, k0 + lr4);
            const float a1 = PSm(r2, k0 + lr4);
            const float a2 = PSm(r1, k0 + lr4 + 4);
            const float a3 = PSm(r2, k0 + lr4 + 4);
#pragma unroll
            for (int nf = 0; nf < 4; nf++) {
                const int cbl = n0 + nf * 8 + lq;
                const float b0 = sV[(k0 + lr4) * 64 +
                                   (((cbl >> 2) ^ lr4) << 2) + (cbl & 3)];
                const float b1 = sV[(k0 + lr4 + 4) * 64 +
                                   (((cbl >> 2) ^ (lr4 + 4)) << 2) + (cbl & 3)];
                mma_tf32(o[nf], a0, a1, a2, a3, b0, b1);
            }
        }
        __syncthreads();   // K/V stage + P fully consumed

        if (j + 2 < jmax) KV_ISSUE(j + 2, (j + 2) & 1);
        CP_COMMIT();
    }

    // ---- normalize + write (tf32-rounded for the out-proj cp.async) ----
    {
        const int r0 = m0 + lq;
        const float il0 = 1.0f / sm[AL + r0];
        const float il1 = 1.0f / sm[AL + r0 + 8];
#pragma unroll
        for (int nf = 0; nf < 4; nf++) {
            const int c0 = n0 + nf * 8 + 2 * lr4;
            const size_t ob0 = ((size_t)(b * Tn + qi * 64 + r0)) * Cn + h * 64 + c0;
            const size_t ob1 = ((size_t)(b * Tn + qi * 64 + r0 + 8)) * Cn + h * 64 + c0;
            *(float2*)&Yg[ob0] = make_float2(cvt_tf32(o[nf][0] * il0),
                                             cvt_tf32(o[nf][1] * il0));
            *(float2*)&Yg[ob1] = make_float2(cvt_tf32(o[nf][2] * il1),
                                             cvt_tf32(o[nf][3] * il1));
        }
    }
#undef KV_ISSUE
}

// ---------------------------------------------------------------------------
extern "C" void kernel_launch(void* const* d_in, const int* in_sizes, int n_in,
                              void* d_out, int out_size)
{
    const float* x  = (const float*)d_in[0];
    const float* Wq = (const float*)d_in[1];
    const float* Wk = (const float*)d_in[2];
    const float* Wv = (const float*)d_in[3];
    const float* Wo = (const float*)d_in[4];
    float* out = (float*)d_out;

    float *q, *k, *v, *y, *xr, *wr;
    cudaGetSymbolAddress((void**)&q,  g_q);
    cudaGetSymbolAddress((void**)&k,  g_k);
    cudaGetSymbolAddress((void**)&v,  g_v);
    cudaGetSymbolAddress((void**)&y,  g_y);
    cudaGetSymbolAddress((void**)&xr, g_xr);
    cudaGetSymbolAddress((void**)&wr, g_wr);
    float* wq_r = wr;
    float* wk_r = wr + (size_t)Cn * Cn;
    float* wv_r = wr + (size_t)2 * Cn * Cn;
    float* wo_r = wr + (size_t)3 * Cn * Cn;

    const int attn_smem = ATTN_SMEM_FLOATS * sizeof(float);   // 100096 B
    cudaFuncSetAttribute(attn_kernel, cudaFuncAttributeMaxDynamicSharedMemorySize, attn_smem);
    cudaFuncSetAttribute(gemm_mma, cudaFuncAttributeMaxDynamicSharedMemorySize, GEMM_SMEM_BYTES);

    // 0) round inputs to tf32 once
    prep_round<<<dim3(4096, 5), 256>>>(x, Wq, Wk, Wv, Wo);
    // 1) QKV projections + fused RoPE
    gemm_mma<<<dim3(Cn / 128, Mrows / 128, 3), 256, GEMM_SMEM_BYTES>>>(
        xr, wq_r, wk_r, wv_r, q, k, v, 1);
    // 2) causal flash attention (q-tile 64, 2 CTAs/SM)
    attn_kernel<<<dim3(Tn / 64, Hn, Bn), 256, attn_smem>>>(q, k, v, y);
    // 3) output projection
    gemm_mma<<<dim3(Cn / 128, Mrows / 128, 1), 256, GEMM_SMEM_BYTES>>>(
        y, wo_r, wo_r, wo_r, out, out, out, 0);
}

// round 13
// speedup vs baseline: 1.2067x; 1.2067x over previous
#include <cuda_runtime.h>
#include <math.h>
#include <cstdint>

// Problem constants
#define Bn 2
#define Tn 2048
#define Cn 1024
#define Hn 16
#define Dn 64
#define Mrows (Bn * Tn)   // 4096

// Scratch (allocation-free), all [B*T, C] row-major
__device__ float g_q[(size_t)Mrows * Cn];
__device__ float g_k[(size_t)Mrows * Cn];
__device__ float g_v[(size_t)Mrows * Cn];
__device__ float g_y[(size_t)Mrows * Cn];
__device__ float g_xr[(size_t)Mrows * Cn];        // tf32-rounded x
__device__ float g_wr[4][(size_t)Cn * Cn];        // tf32-rounded Wq,Wk,Wv,Wo

// ---------------------------------------------------------------------------
// Helpers
// ---------------------------------------------------------------------------
__device__ __forceinline__ float cvt_tf32(float x) {
    float r;
    asm("cvt.rna.tf32.f32 %0, %1;" : "=f"(r) : "f"(x));
    return r;
}
__device__ __forceinline__ uint32_t smem_u32(const void* p) {
    uint32_t a;
    asm("{ .reg .u64 t; cvta.to.shared.u64 t, %1; cvt.u32.u64 %0, t; }" : "=r"(a) : "l"(p));
    return a;
}
__device__ __forceinline__ void cp16(uint32_t dst, const void* src) {
    asm volatile("cp.async.cg.shared.global [%0], [%1], 16;" :: "r"(dst), "l"(src));
}
#define CP_COMMIT() asm volatile("cp.async.commit_group;" ::: "memory")
#define CP_WAIT1()  asm volatile("cp.async.wait_group 1;" ::: "memory")

// ldmatrix x4: four 8x8 b16 tiles == tf32 fragment tiles (32-bit elems as b16 pairs)
__device__ __forceinline__ void ldsm_x4(uint32_t* r, uint32_t addr) {
    asm volatile("ldmatrix.sync.aligned.m8n8.x4.shared.b16 {%0,%1,%2,%3}, [%4];"
                 : "=r"(r[0]), "=r"(r[1]), "=r"(r[2]), "=r"(r[3])
                 : "r"(addr));
}

// D(16x8) += A(16x8) * B(8x8), tf32 inputs as uint regs
__device__ __forceinline__ void mma_tf32r(float* d, const uint32_t* a,
                                          uint32_t b0, uint32_t b1) {
    asm volatile(
        "mma.sync.aligned.m16n8k8.row.col.f32.tf32.tf32.f32 "
        "{%0,%1,%2,%3}, {%4,%5,%6,%7}, {%8,%9}, {%0,%1,%2,%3};"
        : "+f"(d[0]), "+f"(d[1]), "+f"(d[2]), "+f"(d[3])
        : "r"(a[0]), "r"(a[1]), "r"(a[2]), "r"(a[3]), "r"(b0), "r"(b1));
}

// ---------------------------------------------------------------------------
// Prep: round x and the four weight matrices to tf32 (enables raw cp.async)
// ---------------------------------------------------------------------------
__global__ void prep_round(const float* __restrict__ x,
                           const float* __restrict__ wq, const float* __restrict__ wk,
                           const float* __restrict__ wv, const float* __restrict__ wo)
{
    const int seg = blockIdx.y;
    const float* src;
    float* dst;
    int n4;
    if (seg == 0) { src = x;  dst = g_xr;    n4 = Mrows * Cn / 4; }
    else {
        src = (seg == 1) ? wq : (seg == 2) ? wk : (seg == 3) ? wv : wo;
        dst = g_wr[seg - 1];
        n4 = Cn * Cn / 4;
    }
    const int i = blockIdx.x * blockDim.x + threadIdx.x;
    if (i < n4) {
        float4 v = ((const float4*)src)[i];
        v.x = cvt_tf32(v.x); v.y = cvt_tf32(v.y);
        v.z = cvt_tf32(v.z); v.w = cvt_tf32(v.w);
        ((float4*)dst)[i] = v;
    }
}

// ---------------------------------------------------------------------------
// GEMM: C[M,N] = A[M,K] @ W[N,K]^T (tf32 mma.sync + ldmatrix, fp32 accum).
// CTA 128x128, BK=32, 3-stage cp.async, 8 warps (4m x 2n), 32x64 warp tile.
// Smem per stage per matrix: [128 rows][8 chunks of 16B], chunk c at (c ^ (r&7)).
// 2 CTAs/SM. RoPE fused for q,k; tf32 rounding on q,k,v outputs.
// ---------------------------------------------------------------------------
#define GEMM_SMEM_BYTES 98304   // 2 matrices x 3 stages x 16384 B

__global__ __launch_bounds__(256, 2) void gemm_mma(
    const float* __restrict__ A,
    const float* __restrict__ W0, const float* __restrict__ W1, const float* __restrict__ W2,
    float* __restrict__ C0, float* __restrict__ C1, float* __restrict__ C2,
    int do_rope)
{
    extern __shared__ float sm[];
    const uint32_t smbA = smem_u32(sm);
    const uint32_t smbB = smbA + 3 * 16384;

    const int z = blockIdx.z;
    const float* W = (z == 0) ? W0 : ((z == 1) ? W1 : W2);
    float*      Cm = (z == 0) ? C0 : ((z == 1) ? C1 : C2);
    const bool rope = (do_rope != 0) && (z < 2);
    const bool rnd  = (do_rope != 0);

    const int tid = threadIdx.x;
    const int wid = tid >> 5, lane = tid & 31;
    const int warpM = wid >> 1, warpN = wid & 1;
    const int lq = lane >> 2, lr4 = lane & 3;
    const int rowBase = blockIdx.y * 128;
    const int colBase = blockIdx.x * 128;

    // cp.async: row cr (0..127), 4 16B chunks per matrix per thread
    const int cr = tid >> 1, half = tid & 1;
    const float* Ag = A + (size_t)(rowBase + cr) * Cn + half * 16;
    const float* Wg = W + (size_t)(colBase + cr) * Cn + half * 16;
    uint32_t dOf[4];
#pragma unroll
    for (int i = 0; i < 4; i++) {
        const int chunk = half * 4 + i;
        dOf[i] = (uint32_t)((cr * 32 + ((chunk ^ (cr & 7)) << 2)) * 4);
    }

#define G_ISSUE(t, s) do {                                            \
        const float* _ga = Ag + (t) * 32;                             \
        const float* _gw = Wg + (t) * 32;                             \
        const uint32_t _ba = smbA + (s) * 16384;                      \
        const uint32_t _bb = smbB + (s) * 16384;                      \
        _Pragma("unroll")                                             \
        for (int _i = 0; _i < 4; _i++) {                              \
            cp16(_ba + dOf[_i], _ga + _i * 4);                        \
            cp16(_bb + dOf[_i], _gw + _i * 4);                        \
        }                                                             \
    } while (0)

    G_ISSUE(0, 0); CP_COMMIT();
    G_ISSUE(1, 1); CP_COMMIT();

    // ldmatrix per-thread address components
    const int lane15 = lane & 15;
    const int aBit = lane >> 4;            // A: chunk parity
    const int bBit = (lane >> 3) & 1;      // B: chunk parity
    uint32_t aOff[2]; int aSwz[2];
#pragma unroll
    for (int mf = 0; mf < 2; mf++) {
        const int r = warpM * 32 + mf * 16 + lane15;
        aOff[mf] = (uint32_t)(r * 128);    // 8 chunks x 16B per row
        aSwz[mf] = r & 7;
    }
    uint32_t bOff[4]; int bSwz[4];
#pragma unroll
    for (int p = 0; p < 4; p++) {
        const int n = warpN * 64 + p * 16 + ((lane >> 4) << 3) + (lane & 7);
        bOff[p] = (uint32_t)(n * 128);
        bSwz[p] = n & 7;
    }

    float acc[2][8][4];
#pragma unroll
    for (int i = 0; i < 2; i++)
#pragma unroll
        for (int j = 0; j < 8; j++)
#pragma unroll
            for (int k = 0; k < 4; k++) acc[i][j][k] = 0.f;

#pragma unroll 1
    for (int t = 0; t < 32; t++) {
        CP_WAIT1();
        __syncthreads();
        if (t + 2 < 32) G_ISSUE(t + 2, (t + 2) % 3);
        CP_COMMIT();

        const uint32_t sAa = smbA + (t % 3) * 16384;
        const uint32_t sBa = smbB + (t % 3) * 16384;
#pragma unroll
        for (int ks = 0; ks < 4; ks++) {
            uint32_t a[2][4], bf[4][4];
#pragma unroll
            for (int mf = 0; mf < 2; mf++)
                ldsm_x4(a[mf], sAa + aOff[mf] +
                        (uint32_t)((((ks * 2 + aBit) ^ aSwz[mf])) << 4));
#pragma unroll
            for (int p = 0; p < 4; p++)
                ldsm_x4(bf[p], sBa + bOff[p] +
                        (uint32_t)((((ks * 2 + bBit) ^ bSwz[p])) << 4));
#pragma unroll
            for (int nf = 0; nf < 8; nf++) {
                const uint32_t b0 = bf[nf >> 1][(nf & 1) * 2];
                const uint32_t b1 = bf[nf >> 1][(nf & 1) * 2 + 1];
                mma_tf32r(acc[0][nf], a[0], b0, b1);
                mma_tf32r(acc[1][nf], a[1], b0, b1);
            }
        }
    }

    // Epilogue
    const float KLOG = 13.287712379549449f / 32.0f;   // log2(10000)/32
#pragma unroll
    for (int mf = 0; mf < 2; mf++) {
        const int r0 = rowBase + warpM * 32 + mf * 16 + lq;
        if (!rope) {
#pragma unroll
            for (int nf = 0; nf < 8; nf++) {
                const int c0 = colBase + warpN * 64 + nf * 8 + 2 * lr4;
                float v0 = acc[mf][nf][0], v1 = acc[mf][nf][1];
                float v2 = acc[mf][nf][2], v3 = acc[mf][nf][3];
                if (rnd) { v0 = cvt_tf32(v0); v1 = cvt_tf32(v1);
                           v2 = cvt_tf32(v2); v3 = cvt_tf32(v3); }
                *(float2*)&Cm[(size_t)r0 * Cn + c0]       = make_float2(v0, v1);
                *(float2*)&Cm[(size_t)(r0 + 8) * Cn + c0] = make_float2(v2, v3);
            }
        } else {
            const int t0 = r0 & (Tn - 1), t1 = (r0 + 8) & (Tn - 1);
#pragma unroll
            for (int nf = 0; nf < 4; nf++) {       // d in [0,32): partner frag nf+4
                const int dlo = nf * 8 + 2 * lr4;
                const int c0 = colBase + warpN * 64 + dlo;
#pragma unroll
                for (int e = 0; e < 2; e++) {
                    const float freq = exp2f(-(float)(dlo + e) * KLOG);
                    float s0, cth0, s1, cth1;
                    sincosf((float)t0 * freq, &s0, &cth0);
                    sincosf((float)t1 * freq, &s1, &cth1);
                    const float lo0 = acc[mf][nf][e],     hi0 = acc[mf][nf + 4][e];
                    const float lo1 = acc[mf][nf][e + 2], hi1 = acc[mf][nf + 4][e + 2];
                    Cm[(size_t)r0 * Cn + c0 + e]            = cvt_tf32(lo0 * cth0 - hi0 * s0);
                    Cm[(size_t)r0 * Cn + c0 + e + 32]       = cvt_tf32(hi0 * cth0 + lo0 * s0);
                    Cm[(size_t)(r0 + 8) * Cn + c0 + e]      = cvt_tf32(lo1 * cth1 - hi1 * s1);
                    Cm[(size_t)(r0 + 8) * Cn + c0 + e + 32] = cvt_tf32(hi1 * cth1 + lo1 * s1);
                }
            }
        }
    }
#undef G_ISSUE
}

// ---------------------------------------------------------------------------
// Flash attention, tf32 mma.sync + ldmatrix; q-tile=128, k-tile=64, 3-stage
// cp.async K/V. 256 threads, 8 warps (4m x 2n), warp tile 32x32.
// Q/K/V swizzled [row][16 chunks]; P stride-68 (rows 16B-aligned, LDSM-friendly).
// ---------------------------------------------------------------------------
#define AQ 0
#define AK 8192
#define AV 20480
#define AP 32768
#define AM 41472
#define AL 41600
#define AA 41728
#define ATTN_SMEM_FLOATS 41856
#define PSm(m, c) sm[AP + (m) * 68 + (c)]

__global__ __launch_bounds__(256) void attn_kernel(
    const float* __restrict__ Qg, const float* __restrict__ Kg,
    const float* __restrict__ Vg, float* __restrict__ Yg)
{
    extern __shared__ float sm[];
    const uint32_t smb = smem_u32(sm);
    const int qi = (int)(gridDim.x - 1 - blockIdx.x);   // long tiles first
    const int h = blockIdx.y, b = blockIdx.z;
    const int tid = threadIdx.x;
    const int wid = tid >> 5, lane = tid & 31;
    const int wM = wid >> 1, wN = wid & 1;
    const int lq = lane >> 2, lr4 = lane & 3;
    const int m0 = wM * 32, n0 = wN * 32;

    // cp.async mappings
    const int qr = tid >> 1, qci = tid & 1;             // Q: 128 rows x 2 col-halves
    const float* Qp = Qg + (size_t)(b * Tn + qi * 128 + qr) * Cn + h * 64 + qci * 32;
    const int kr = tid >> 2, kci = tid & 3;             // K/V: 64 rows x 4 col-quarters
    const float* Kp = Kg + (size_t)(b * Tn + kr) * Cn + h * 64 + kci * 16;
    const float* Vp = Vg + (size_t)(b * Tn + kr) * Cn + h * 64 + kci * 16;

#define KV_ISSUE(j, s) do {                                                     \
        const float* _kp = Kp + (size_t)((j) * 64) * Cn;                        \
        const float* _vp = Vp + (size_t)((j) * 64) * Cn;                        \
        const uint32_t _bk = smb + (uint32_t)((AK + (s) * 4096) * 4);           \
        const uint32_t _bv = smb + (uint32_t)((AV + (s) * 4096) * 4);           \
        _Pragma("unroll")                                                       \
        for (int _i = 0; _i < 4; _i++) {                                        \
            const int _c = kci * 4 + _i;                                        \
            const uint32_t _off = (uint32_t)((kr * 64 + ((_c ^ (kr & 7)) << 2)) * 4); \
            cp16(_bk + _off, _kp + _i * 4);                                     \
            cp16(_bv + _off, _vp + _i * 4);                                     \
        }                                                                       \
    } while (0)

    // Prologue: group0 = Q + KV(0); group1 = KV(1)
#pragma unroll
    for (int i = 0; i < 8; i++) {
        const int c = qci * 8 + i;
        cp16(smb + (uint32_t)((qr * 64 + ((c ^ (qr & 7)) << 2)) * 4), Qp + i * 4);
    }
    KV_ISSUE(0, 0); CP_COMMIT();
    KV_ISSUE(1, 1); CP_COMMIT();

    if (tid < 128) { sm[AM + tid] = -1e30f; sm[AL + tid] = 0.f; }

    // ldmatrix address components
    const int lane15 = lane & 15;
    const int aBit = lane >> 4;
    const int bBit = (lane >> 3) & 1;
    uint32_t qOff[2]; int qSwz[2];
#pragma unroll
    for (int mf = 0; mf < 2; mf++) {
        const int r = m0 + mf * 16 + lane15;
        qOff[mf] = (uint32_t)(r * 256);    // 16 chunks x 16B
        qSwz[mf] = r & 7;
        // P rows: stride 68 floats = 272 B, no swizzle
    }
    uint32_t kOff[2]; int kSwz[2];
#pragma unroll
    for (int p = 0; p < 2; p++) {
        const int n = n0 + p * 16 + ((lane >> 4) << 3) + (lane & 7);
        kOff[p] = (uint32_t)(n * 256);
        kSwz[p] = n & 7;
    }
    uint32_t pOff[2];
#pragma unroll
    for (int mf = 0; mf < 2; mf++)
        pOff[mf] = (uint32_t)(AP * 4 + (m0 + mf * 16 + lane15) * 272);

    float o[2][4][4];
#pragma unroll
    for (int i = 0; i < 2; i++)
#pragma unroll
        for (int j = 0; j < 4; j++)
#pragma unroll
            for (int k = 0; k < 4; k++) o[i][j][k] = 0.f;

    const int jmax = 2 * qi + 2;
#pragma unroll 1
    for (int j = 0; j < jmax; j++) {
        CP_WAIT1();
        __syncthreads();
        if (j + 2 < jmax) KV_ISSUE(j + 2, (j + 2) % 3);
        CP_COMMIT();

        const uint32_t sQa = smb;                                      // AQ = 0
        const uint32_t sKa = smb + (uint32_t)((AK + (j % 3) * 4096) * 4);
        const float*   sV  = sm + AV + (j % 3) * 4096;

        // ---- S = Q K^T (warp tile 32x32) ----
        float s[2][4][4];
#pragma unroll
        for (int i = 0; i < 2; i++)
#pragma unroll
            for (int jj = 0; jj < 4; jj++)
#pragma unroll
                for (int k = 0; k < 4; k++) s[i][jj][k] = 0.f;
#pragma unroll
        for (int kd = 0; kd < 8; kd++) {
            uint32_t a[2][4], bf[2][4];
#pragma unroll
            for (int mf = 0; mf < 2; mf++)
                ldsm_x4(a[mf], sQa + qOff[mf] +
                        (uint32_t)((((kd * 2 + aBit) ^ qSwz[mf])) << 4));
#pragma unroll
            for (int p = 0; p < 2; p++)
                ldsm_x4(bf[p], sKa + kOff[p] +
                        (uint32_t)((((kd * 2 + bBit) ^ kSwz[p])) << 4));
#pragma unroll
            for (int nf = 0; nf < 4; nf++) {
                const uint32_t b0 = bf[nf >> 1][(nf & 1) * 2];
                const uint32_t b1 = bf[nf >> 1][(nf & 1) * 2 + 1];
                mma_tf32r(s[0][nf], a[0], b0, b1);
                mma_tf32r(s[1][nf], a[1], b0, b1);
            }
        }

        // ---- scale + mask + store S to P ----
        const bool need_mask = (j >= 2 * qi);
#pragma unroll
        for (int mf = 0; mf < 2; mf++) {
            const int r0 = m0 + mf * 16 + lq;
#pragma unroll
            for (int nf = 0; nf < 4; nf++) {
                const int c0 = n0 + nf * 8 + 2 * lr4;
                float v0 = s[mf][nf][0] * 0.125f, v1 = s[mf][nf][1] * 0.125f;
                float v2 = s[mf][nf][2] * 0.125f, v3 = s[mf][nf][3] * 0.125f;
                if (need_mask) {
                    const int mg0 = qi * 128 + r0, mg1 = mg0 + 8;
                    const int cg0 = j * 64 + c0, cg1 = cg0 + 1;
                    if (cg0 > mg0) v0 = -1e30f;
                    if (cg1 > mg0) v1 = -1e30f;
                    if (cg0 > mg1) v2 = -1e30f;
                    if (cg1 > mg1) v3 = -1e30f;
                }
                *(float2*)&PSm(r0, c0)     = make_float2(v0, v1);
                *(float2*)&PSm(r0 + 8, c0) = make_float2(v2, v3);
            }
        }
        __syncthreads();

        // ---- online softmax: 2 threads per row ----
        {
            const int r = tid >> 1;
            const int ch = (tid & 1) * 32;
            const float m_old = sm[AM + r];
            float mx = m_old;
#pragma unroll
            for (int c = 0; c < 32; c++) mx = fmaxf(mx, PSm(r, ch + c));
            mx = fmaxf(mx, __shfl_xor_sync(0xffffffffu, mx, 1));
            const float alpha = __expf(m_old - mx);
            float ssum = 0.f;
#pragma unroll
            for (int c = 0; c < 32; c++) {
                float p = __expf(PSm(r, ch + c) - mx);
                PSm(r, ch + c) = cvt_tf32(p);
                ssum += p;
            }
            ssum += __shfl_xor_sync(0xffffffffu, ssum, 1);
            sm[AM + r] = mx;
            sm[AA + r] = alpha;
            sm[AL + r] = sm[AL + r] * alpha + ssum;
        }
        __syncthreads();

        // ---- O = O*alpha + P V ----
        float al[2][2];
#pragma unroll
        for (int mf = 0; mf < 2; mf++) {
            al[mf][0] = sm[AA + m0 + mf * 16 + lq];
            al[mf][1] = sm[AA + m0 + mf * 16 + lq + 8];
        }
#pragma unroll
        for (int mf = 0; mf < 2; mf++)
#pragma unroll
            for (int nf = 0; nf < 4; nf++) {
                o[mf][nf][0] *= al[mf][0]; o[mf][nf][1] *= al[mf][0];
                o[mf][nf][2] *= al[mf][1]; o[mf][nf][3] *= al[mf][1];
            }
#pragma unroll
        for (int kc = 0; kc < 8; kc++) {
            const int k0 = kc * 8;
            uint32_t a[2][4];
#pragma unroll
            for (int mf = 0; mf < 2; mf++)
                ldsm_x4(a[mf], smb + pOff[mf] + (uint32_t)((kc * 2 + aBit) << 4));
#pragma unroll
            for (int nf = 0; nf < 4; nf++) {
                const int cbl = n0 + nf * 8 + lq;
                const float b0f = sV[(k0 + lr4) * 64 +
                                    (((cbl >> 2) ^ lr4) << 2) + (cbl & 3)];
                const float b1f = sV[(k0 + lr4 + 4) * 64 +
                                    (((cbl >> 2) ^ (lr4 + 4)) << 2) + (cbl & 3)];
                const uint32_t b0 = __float_as_uint(b0f);
                const uint32_t b1 = __float_as_uint(b1f);
                mma_tf32r(o[0][nf], a[0], b0, b1);
                mma_tf32r(o[1][nf], a[1], b0, b1);
            }
        }
        // next-iteration top sync protects P/V reuse
    }

    // ---- normalize + write (tf32-rounded for the out-proj cp.async) ----
#pragma unroll
    for (int mf = 0; mf < 2; mf++) {
        const int r0 = m0 + mf * 16 + lq;
        const float il0 = 1.0f / sm[AL + r0];
        const float il1 = 1.0f / sm[AL + r0 + 8];
#pragma unroll
        for (int nf = 0; nf < 4; nf++) {
            const int c0 = n0 + nf * 8 + 2 * lr4;
            const size_t ob0 = ((size_t)(b * Tn + qi * 128 + r0)) * Cn + h * 64 + c0;
            const size_t ob1 = ((size_t)(b * Tn + qi * 128 + r0 + 8)) * Cn + h * 64 + c0;
            *(float2*)&Yg[ob0] = make_float2(cvt_tf32(o[0 + mf][nf][0] * il0),
                                             cvt_tf32(o[mf][nf][1] * il0));
            *(float2*)&Yg[ob1] = make_float2(cvt_tf32(o[mf][nf][2] * il1),
                                             cvt_tf32(o[mf][nf][3] * il1));
        }
    }
#undef KV_ISSUE
}

// ---------------------------------------------------------------------------
extern "C" void kernel_launch(void* const* d_in, const int* in_sizes, int n_in,
                              void* d_out, int out_size)
{
    const float* x  = (const float*)d_in[0];
    const float* Wq = (const float*)d_in[1];
    const float* Wk = (const float*)d_in[2];
    const float* Wv = (const float*)d_in[3];
    const float* Wo = (const float*)d_in[4];
    float* out = (float*)d_out;

    float *q, *k, *v, *y, *xr, *wr;
    cudaGetSymbolAddress((void**)&q,  g_q);
    cudaGetSymbolAddress((void**)&k,  g_k);
    cudaGetSymbolAddress((void**)&v,  g_v);
    cudaGetSymbolAddress((void**)&y,  g_y);
    cudaGetSymbolAddress((void**)&xr, g_xr);
    cudaGetSymbolAddress((void**)&wr, g_wr);
    float* wq_r = wr;
    float* wk_r = wr + (size_t)Cn * Cn;
    float* wv_r = wr + (size_t)2 * Cn * Cn;
    float* wo_r = wr + (size_t)3 * Cn * Cn;

    const int attn_smem = ATTN_SMEM_FLOATS * sizeof(float);   // 167424 B
    cudaFuncSetAttribute(attn_kernel, cudaFuncAttributeMaxDynamicSharedMemorySize, attn_smem);
    cudaFuncSetAttribute(gemm_mma, cudaFuncAttributeMaxDynamicSharedMemorySize, GEMM_SMEM_BYTES);

    // 0) round inputs to tf32 once
    prep_round<<<dim3(4096, 5), 256>>>(x, Wq, Wk, Wv, Wo);
    // 1) QKV projections + fused RoPE
    gemm_mma<<<dim3(Cn / 128, Mrows / 128, 3), 256, GEMM_SMEM_BYTES>>>(
        xr, wq_r, wk_r, wv_r, q, k, v, 1);
    // 2) causal flash attention (q-tile 128, ldmatrix frags)
    attn_kernel<<<dim3(Tn / 128, Hn, Bn), 256, attn_smem>>>(q, k, v, y);
    // 3) output projection
    gemm_mma<<<dim3(Cn / 128, Mrows / 128, 1), 256, GEMM_SMEM_BYTES>>>(
        y, wo_r, wo_r, wo_r, out, out, out, 0);
}

// round 14
// speedup vs baseline: 2.0446x; 1.6943x over previous
#include <cuda_runtime.h>
#include <cuda_fp16.h>
#include <math.h>
#include <cstdint>

// Problem constants
#define Bn 2
#define Tn 2048
#define Cn 1024
#define Hn 16
#define Dn 64
#define Mrows (Bn * Tn)   // 4096

// Scratch (allocation-free). fp16 everywhere except final output.
__device__ __half g_q[(size_t)Mrows * Cn];
__device__ __half g_k[(size_t)Mrows * Cn];
__device__ __half g_v[(size_t)Mrows * Cn];
__device__ __half g_y[(size_t)Mrows * Cn];
__device__ __half g_xh[(size_t)Mrows * Cn];       // fp16 x
__device__ __half g_wh[4][(size_t)Cn * Cn];       // fp16 Wq,Wk,Wv,Wo

// ---------------------------------------------------------------------------
// Helpers
// ---------------------------------------------------------------------------
__device__ __forceinline__ uint32_t smem_u32(const void* p) {
    uint32_t a;
    asm("{ .reg .u64 t; cvta.to.shared.u64 t, %1; cvt.u32.u64 %0, t; }" : "=r"(a) : "l"(p));
    return a;
}
__device__ __forceinline__ void cp16(uint32_t dst, const void* src) {
    asm volatile("cp.async.cg.shared.global [%0], [%1], 16;" :: "r"(dst), "l"(src));
}
#define CP_COMMIT() asm volatile("cp.async.commit_group;" ::: "memory")
#define CP_WAIT1()  asm volatile("cp.async.wait_group 1;" ::: "memory")

__device__ __forceinline__ void ldsm_x4(uint32_t* r, uint32_t addr) {
    asm volatile("ldmatrix.sync.aligned.m8n8.x4.shared.b16 {%0,%1,%2,%3}, [%4];"
                 : "=r"(r[0]), "=r"(r[1]), "=r"(r[2]), "=r"(r[3]) : "r"(addr));
}
__device__ __forceinline__ void ldsm_x4_t(uint32_t* r, uint32_t addr) {
    asm volatile("ldmatrix.sync.aligned.m8n8.x4.trans.shared.b16 {%0,%1,%2,%3}, [%4];"
                 : "=r"(r[0]), "=r"(r[1]), "=r"(r[2]), "=r"(r[3]) : "r"(addr));
}

// D(16x8) += A(16x16) * B(16x8), fp16 inputs, fp32 accum
__device__ __forceinline__ void mma_f16(float* d, const uint32_t* a,
                                        uint32_t b0, uint32_t b1) {
    asm volatile(
        "mma.sync.aligned.m16n8k16.row.col.f32.f16.f16.f32 "
        "{%0,%1,%2,%3}, {%4,%5,%6,%7}, {%8,%9}, {%0,%1,%2,%3};"
        : "+f"(d[0]), "+f"(d[1]), "+f"(d[2]), "+f"(d[3])
        : "r"(a[0]), "r"(a[1]), "r"(a[2]), "r"(a[3]), "r"(b0), "r"(b1));
}

// ---------------------------------------------------------------------------
// Prep: convert x and weights to fp16
// ---------------------------------------------------------------------------
__global__ void prep_h(const float* __restrict__ x,
                       const float* __restrict__ wq, const float* __restrict__ wk,
                       const float* __restrict__ wv, const float* __restrict__ wo)
{
    const int seg = blockIdx.y;
    const float* src;
    __half* dst;
    int n2;
    if (seg == 0) { src = x; dst = g_xh; n2 = Mrows * Cn / 2; }
    else {
        src = (seg == 1) ? wq : (seg == 2) ? wk : (seg == 3) ? wv : wo;
        dst = g_wh[seg - 1];
        n2 = Cn * Cn / 2;
    }
    const int i = blockIdx.x * blockDim.x + threadIdx.x;
    if (i < n2) {
        float2 v = ((const float2*)src)[i];
        ((__half2*)dst)[i] = __float22half2_rn(v);
    }
}

// ---------------------------------------------------------------------------
// GEMM: C[M,N] = A[M,K] @ W[N,K]^T (fp16 mma.m16n8k16 + ldmatrix, fp32 accum).
// CTA 128x128, BK=64 halfs (128B rows), 3-stage cp.async, 8 warps (4m x 2n),
// warp tile 32x64. Smem rows: 8 chunks of 16B, chunk c at (c ^ (r&7)).
// OH=true: fp16 output (+optional fused RoPE). OH=false: fp32 output.
// ---------------------------------------------------------------------------
#define GEMM_SMEM_BYTES 98304   // 2 matrices x 3 stages x 16384 B

template <bool OH>
__global__ __launch_bounds__(256, 2) void gemm_h(
    const __half* __restrict__ A,
    const __half* __restrict__ W0, const __half* __restrict__ W1, const __half* __restrict__ W2,
    void* __restrict__ C0v, void* __restrict__ C1v, void* __restrict__ C2v,
    int do_rope)
{
    extern __shared__ char smc[];
    const uint32_t smbA = smem_u32(smc);
    const uint32_t smbB = smbA + 3 * 16384;

    const int z = blockIdx.z;
    const __half* W = (z == 0) ? W0 : ((z == 1) ? W1 : W2);
    void*        Cv = (z == 0) ? C0v : ((z == 1) ? C1v : C2v);
    const bool rope = (do_rope != 0) && (z < 2);

    const int tid = threadIdx.x;
    const int wid = tid >> 5, lane = tid & 31;
    const int warpM = wid >> 1, warpN = wid & 1;
    const int lq = lane >> 2, lr4 = lane & 3;
    const int rowBase = blockIdx.y * 128;
    const int colBase = blockIdx.x * 128;

    // cp.async: row cr (0..127), 2 threads/row, 4 16B chunks each per matrix
    const int cr = tid >> 1, hlf = tid & 1;
    const __half* Ag = A + (size_t)(rowBase + cr) * Cn + hlf * 32;
    const __half* Wg = W + (size_t)(colBase + cr) * Cn + hlf * 32;
    uint32_t dOf[4];
#pragma unroll
    for (int i = 0; i < 4; i++) {
        const int chunk = hlf * 4 + i;
        dOf[i] = (uint32_t)(cr * 128 + ((chunk ^ (cr & 7)) << 4));
    }

#define G_ISSUE(t, s) do {                                            \
        const __half* _ga = Ag + (t) * 64;                            \
        const __half* _gw = Wg + (t) * 64;                            \
        const uint32_t _ba = smbA + (s) * 16384;                      \
        const uint32_t _bb = smbB + (s) * 16384;                      \
        _Pragma("unroll")                                             \
        for (int _i = 0; _i < 4; _i++) {                              \
            cp16(_ba + dOf[_i], _ga + _i * 8);                        \
            cp16(_bb + dOf[_i], _gw + _i * 8);                        \
        }                                                             \
    } while (0)

    G_ISSUE(0, 0); CP_COMMIT();
    G_ISSUE(1, 1); CP_COMMIT();

    // ldmatrix address components
    const int lane15 = lane & 15;
    const int aBit = lane >> 4;            // A: k-chunk parity
    const int bBit = (lane >> 3) & 1;      // B: k-chunk parity
    uint32_t aOff[2]; int aSwz[2];
#pragma unroll
    for (int mf = 0; mf < 2; mf++) {
        const int r = warpM * 32 + mf * 16 + lane15;
        aOff[mf] = (uint32_t)(r * 128);
        aSwz[mf] = r & 7;
    }
    uint32_t bOff[4]; int bSwz[4];
#pragma unroll
    for (int p = 0; p < 4; p++) {
        const int n = warpN * 64 + p * 16 + ((lane >> 4) << 3) + (lane & 7);
        bOff[p] = (uint32_t)(n * 128);
        bSwz[p] = n & 7;
    }

    float acc[2][8][4];
#pragma unroll
    for (int i = 0; i < 2; i++)
#pragma unroll
        for (int j = 0; j < 8; j++)
#pragma unroll
            for (int k = 0; k < 4; k++) acc[i][j][k] = 0.f;

#pragma unroll 1
    for (int t = 0; t < 16; t++) {
        CP_WAIT1();
        __syncthreads();
        if (t + 2 < 16) G_ISSUE(t + 2, (t + 2) % 3);
        CP_COMMIT();

        const uint32_t sAa = smbA + (t % 3) * 16384;
        const uint32_t sBa = smbB + (t % 3) * 16384;
#pragma unroll
        for (int ks = 0; ks < 4; ks++) {          // k16 steps (BK=64)
            uint32_t a[2][4], bf[4][4];
#pragma unroll
            for (int mf = 0; mf < 2; mf++)
                ldsm_x4(a[mf], sAa + aOff[mf] +
                        (uint32_t)(((ks * 2 + aBit) ^ aSwz[mf]) << 4));
#pragma unroll
            for (int p = 0; p < 4; p++)
                ldsm_x4(bf[p], sBa + bOff[p] +
                        (uint32_t)(((ks * 2 + bBit) ^ bSwz[p]) << 4));
#pragma unroll
            for (int nf = 0; nf < 8; nf++) {
                const uint32_t b0 = bf[nf >> 1][(nf & 1) * 2];
                const uint32_t b1 = bf[nf >> 1][(nf & 1) * 2 + 1];
                mma_f16(acc[0][nf], a[0], b0, b1);
                mma_f16(acc[1][nf], a[1], b0, b1);
            }
        }
    }

    // Epilogue
    const float KLOG = 13.287712379549449f / 32.0f;   // log2(10000)/32
#pragma unroll
    for (int mf = 0; mf < 2; mf++) {
        const int r0 = rowBase + warpM * 32 + mf * 16 + lq;
        if (OH) {
            __half* Cm = (__half*)Cv;
            if (!rope) {
#pragma unroll
                for (int nf = 0; nf < 8; nf++) {
                    const int c0 = colBase + warpN * 64 + nf * 8 + 2 * lr4;
                    *(__half2*)&Cm[(size_t)r0 * Cn + c0] =
                        __float22half2_rn(make_float2(acc[mf][nf][0], acc[mf][nf][1]));
                    *(__half2*)&Cm[(size_t)(r0 + 8) * Cn + c0] =
                        __float22half2_rn(make_float2(acc[mf][nf][2], acc[mf][nf][3]));
                }
            } else {
                const int t0 = r0 & (Tn - 1), t1 = (r0 + 8) & (Tn - 1);
#pragma unroll
                for (int nf = 0; nf < 4; nf++) {   // d in [0,32): partner frag nf+4
                    const int dlo = nf * 8 + 2 * lr4;
                    const int c0 = colBase + warpN * 64 + dlo;
#pragma unroll
                    for (int e = 0; e < 2; e++) {
                        const float freq = exp2f(-(float)(dlo + e) * KLOG);
                        float s0, cth0, s1, cth1;
                        sincosf((float)t0 * freq, &s0, &cth0);
                        sincosf((float)t1 * freq, &s1, &cth1);
                        const float lo0 = acc[mf][nf][e],     hi0 = acc[mf][nf + 4][e];
                        const float lo1 = acc[mf][nf][e + 2], hi1 = acc[mf][nf + 4][e + 2];
                        Cm[(size_t)r0 * Cn + c0 + e]            = __float2half_rn(lo0 * cth0 - hi0 * s0);
                        Cm[(size_t)r0 * Cn + c0 + e + 32]       = __float2half_rn(hi0 * cth0 + lo0 * s0);
                        Cm[(size_t)(r0 + 8) * Cn + c0 + e]      = __float2half_rn(lo1 * cth1 - hi1 * s1);
                        Cm[(size_t)(r0 + 8) * Cn + c0 + e + 32] = __float2half_rn(hi1 * cth1 + lo1 * s1);
                    }
                }
            }
        } else {
            float* Cm = (float*)Cv;
#pragma unroll
            for (int nf = 0; nf < 8; nf++) {
                const int c0 = colBase + warpN * 64 + nf * 8 + 2 * lr4;
                *(float2*)&Cm[(size_t)r0 * Cn + c0] =
                    make_float2(acc[mf][nf][0], acc[mf][nf][1]);
                *(float2*)&Cm[(size_t)(r0 + 8) * Cn + c0] =
                    make_float2(acc[mf][nf][2], acc[mf][nf][3]);
            }
        }
    }
#undef G_ISSUE
}

// ---------------------------------------------------------------------------
// Flash attention, fp16 mma + ldmatrix (V via ldmatrix.trans).
// q-tile=128, k-tile=64, 3-stage cp.async K/V, 256 threads, 8 warps (4m x 2n).
// All tiles: rows of 128B (64 halfs), 8 chunks of 16B, chunk c at (c ^ (r&7)).
// Smem bytes: Q 16384 | K 3x8192 | V 3x8192 | P 16384 | stats 1536 = 83456.
// ---------------------------------------------------------------------------
#define QB 0
#define KB 16384
#define VB 40960
#define PB 65536
#define MB 81920
#define LB 82432
#define AB 82944
#define ATTN_SMEM_BYTES 83456

__global__ __launch_bounds__(256, 2) void attn_h(
    const __half* __restrict__ Qg, const __half* __restrict__ Kg,
    const __half* __restrict__ Vg, __half* __restrict__ Yg)
{
    extern __shared__ char smc[];
    const uint32_t smb = smem_u32(smc);
    float* stM = (float*)(smc + MB);
    float* stL = (float*)(smc + LB);
    float* stA = (float*)(smc + AB);

    const int qi = (int)(gridDim.x - 1 - blockIdx.x);   // long tiles first
    const int h = blockIdx.y, b = blockIdx.z;
    const int tid = threadIdx.x;
    const int wid = tid >> 5, lane = tid & 31;
    const int wM = wid >> 1, wN = wid & 1;
    const int lq = lane >> 2, lr4 = lane & 3;
    const int m0 = wM * 32, n0 = wN * 32;

    // cp.async mappings
    const int qr = tid >> 1, qci = tid & 1;             // Q: 128 rows, 2 thr/row
    const __half* Qp = Qg + (size_t)(b * Tn + qi * 128 + qr) * Cn + h * 64 + qci * 32;
    const int kr = tid >> 2, kci = tid & 3;             // K/V: 64 rows, 4 thr/row
    const __half* Kp = Kg + (size_t)(b * Tn + kr) * Cn + h * 64 + kci * 16;
    const __half* Vp = Vg + (size_t)(b * Tn + kr) * Cn + h * 64 + kci * 16;
    uint32_t kvOf[2];
#pragma unroll
    for (int i = 0; i < 2; i++) {
        const int chunk = kci * 2 + i;
        kvOf[i] = (uint32_t)(kr * 128 + ((chunk ^ (kr & 7)) << 4));
    }

#define KV_ISSUE(j, s) do {                                                     \
        const __half* _kp = Kp + (size_t)((j) * 64) * Cn;                       \
        const __half* _vp = Vp + (size_t)((j) * 64) * Cn;                       \
        const uint32_t _bk = smb + KB + (s) * 8192;                             \
        const uint32_t _bv = smb + VB + (s) * 8192;                             \
        cp16(_bk + kvOf[0], _kp);     cp16(_bk + kvOf[1], _kp + 8);             \
        cp16(_bv + kvOf[0], _vp);     cp16(_bv + kvOf[1], _vp + 8);             \
    } while (0)

    // Prologue: Q (4 chunks/thread) + KV(0) in group0; KV(1) group1
#pragma unroll
    for (int i = 0; i < 4; i++) {
        const int chunk = qci * 4 + i;
        cp16(smb + QB + (uint32_t)(qr * 128 + ((chunk ^ (qr & 7)) << 4)), Qp + i * 8);
    }
    KV_ISSUE(0, 0); CP_COMMIT();
    KV_ISSUE(1, 1); CP_COMMIT();

    if (tid < 128) { stM[tid] = -1e30f; stL[tid] = 0.f; }

    // ldmatrix address components
    const int lane15 = lane & 15;
    const int aBit = lane >> 4;
    uint32_t qOff[2]; int qSwz[2];
#pragma unroll
    for (int mf = 0; mf < 2; mf++) {
        const int r = m0 + mf * 16 + lane15;
        qOff[mf] = (uint32_t)(r * 128);
        qSwz[mf] = r & 7;
    }
    uint32_t kOff[2]; int kSwz[2];
#pragma unroll
    for (int p = 0; p < 2; p++) {
        const int n = n0 + p * 16 + ((lane >> 4) << 3) + (lane & 7);
        kOff[p] = (uint32_t)(n * 128);
        kSwz[p] = n & 7;
    }
    // V trans: lane -> k-row and n-chunk
    const int vkl = ((lane >> 3) & 1) * 8 + (lane & 7);   // k-row within 16
    const int vnc = (n0 >> 3) + (lane >> 4);              // n-chunk (+p*2 later)

    float o[2][4][4];
#pragma unroll
    for (int i = 0; i < 2; i++)
#pragma unroll
        for (int j = 0; j < 4; j++)
#pragma unroll
            for (int k = 0; k < 4; k++) o[i][j][k] = 0.f;

    const int jmax = 2 * qi + 2;
#pragma unroll 1
    for (int j = 0; j < jmax; j++) {
        CP_WAIT1();
        __syncthreads();
        if (j + 2 < jmax) KV_ISSUE(j + 2, (j + 2) % 3);
        CP_COMMIT();

        const uint32_t sQa = smb + QB;
        const uint32_t sKa = smb + KB + (j % 3) * 8192;
        const uint32_t sVa = smb + VB + (j % 3) * 8192;

        // ---- S = Q K^T (k=64 -> 4 k16 steps) ----
        float s[2][4][4];
#pragma unroll
        for (int i = 0; i < 2; i++)
#pragma unroll
            for (int jj = 0; jj < 4; jj++)
#pragma unroll
                for (int k = 0; k < 4; k++) s[i][jj][k] = 0.f;
#pragma unroll
        for (int ks = 0; ks < 4; ks++) {
            uint32_t a[2][4], bf[2][4];
#pragma unroll
            for (int mf = 0; mf < 2; mf++)
                ldsm_x4(a[mf], sQa + qOff[mf] +
                        (uint32_t)(((ks * 2 + aBit) ^ qSwz[mf]) << 4));
#pragma unroll
            for (int p = 0; p < 2; p++)
                ldsm_x4(bf[p], sKa + kOff[p] +
                        (uint32_t)(((ks * 2 + ((lane >> 3) & 1)) ^ kSwz[p]) << 4));
#pragma unroll
            for (int nf = 0; nf < 4; nf++) {
                const uint32_t b0 = bf[nf >> 1][(nf & 1) * 2];
                const uint32_t b1 = bf[nf >> 1][(nf & 1) * 2 + 1];
                mma_f16(s[0][nf], a[0], b0, b1);
                mma_f16(s[1][nf], a[1], b0, b1);
            }
        }

        // ---- scale + mask + store S to P (fp16, swizzled) ----
        const bool need_mask = (j >= 2 * qi);
#pragma unroll
        for (int mf = 0; mf < 2; mf++) {
            const int r0 = m0 + mf * 16 + lq;
#pragma unroll
            for (int nf = 0; nf < 4; nf++) {
                const int c0 = n0 + nf * 8 + 2 * lr4;
                float v0 = s[mf][nf][0] * 0.125f, v1 = s[mf][nf][1] * 0.125f;
                float v2 = s[mf][nf][2] * 0.125f, v3 = s[mf][nf][3] * 0.125f;
                if (need_mask) {
                    const int mg0 = qi * 128 + r0, mg1 = mg0 + 8;
                    const int cg0 = j * 64 + c0, cg1 = cg0 + 1;
                    if (cg0 > mg0) v0 = -60000.f;
                    if (cg1 > mg0) v1 = -60000.f;
                    if (cg0 > mg1) v2 = -60000.f;
                    if (cg1 > mg1) v3 = -60000.f;
                }
                const uint32_t cb = (uint32_t)((((c0 >> 3)) << 4) + (c0 & 7) * 2);
                *(__half2*)(smc + PB + r0 * 128 +
                            ((((c0 >> 3) ^ (r0 & 7))) << 4) + (c0 & 7) * 2) =
                    __float22half2_rn(make_float2(v0, v1));
                *(__half2*)(smc + PB + (r0 + 8) * 128 +
                            ((((c0 >> 3) ^ ((r0 + 8) & 7))) << 4) + (c0 & 7) * 2) =
                    __float22half2_rn(make_float2(v2, v3));
                (void)cb;
            }
        }
        __syncthreads();

        // ---- online softmax: 2 threads per row, two passes over fp16 P ----
        {
            const int r = tid >> 1;
            const int ch = (tid & 1) * 32;
            const float m_old = stM[r];
            float mx = m_old;
#pragma unroll
            for (int c2 = 0; c2 < 16; c2++) {
                const int col = ch + c2 * 2;
                const __half2 hv = *(const __half2*)(smc + PB + r * 128 +
                    ((((col >> 3) ^ (r & 7))) << 4) + (col & 7) * 2);
                const float2 f = __half22float2(hv);
                mx = fmaxf(mx, fmaxf(f.x, f.y));
            }
            mx = fmaxf(mx, __shfl_xor_sync(0xffffffffu, mx, 1));
            const float alpha = __expf(m_old - mx);
            float ssum = 0.f;
#pragma unroll
            for (int c2 = 0; c2 < 16; c2++) {
                const int col = ch + c2 * 2;
                __half2* hp = (__half2*)(smc + PB + r * 128 +
                    ((((col >> 3) ^ (r & 7))) << 4) + (col & 7) * 2);
                const float2 f = __half22float2(*hp);
                const float p0 = __expf(f.x - mx);
                const float p1 = __expf(f.y - mx);
                *hp = __float22half2_rn(make_float2(p0, p1));
                ssum += p0 + p1;
            }
            ssum += __shfl_xor_sync(0xffffffffu, ssum, 1);
            stM[r] = mx;
            stA[r] = alpha;
            stL[r] = stL[r] * alpha + ssum;
        }
        __syncthreads();

        // ---- O = O*alpha + P V ----
        float al[2][2];
#pragma unroll
        for (int mf = 0; mf < 2; mf++) {
            al[mf][0] = stA[m0 + mf * 16 + lq];
            al[mf][1] = stA[m0 + mf * 16 + lq + 8];
        }
#pragma unroll
        for (int mf = 0; mf < 2; mf++)
#pragma unroll
            for (int nf = 0; nf < 4; nf++) {
                o[mf][nf][0] *= al[mf][0]; o[mf][nf][1] *= al[mf][0];
                o[mf][nf][2] *= al[mf][1]; o[mf][nf][3] *= al[mf][1];
            }
#pragma unroll
        for (int kc = 0; kc < 4; kc++) {          // k=64 -> 4 k16 steps
            uint32_t a[2][4];
#pragma unroll
            for (int mf = 0; mf < 2; mf++) {
                const int r = m0 + mf * 16 + lane15;
                a[mf][0] = 0;   // placeholder, loaded below
                ldsm_x4(a[mf], smb + PB + (uint32_t)(r * 128) +
                        (uint32_t)(((kc * 2 + aBit) ^ (r & 7)) << 4));
            }
#pragma unroll
            for (int p = 0; p < 2; p++) {
                const int krow = kc * 16 + vkl;
                const int nchunk = vnc + p * 2;
                uint32_t bt[4];
                ldsm_x4_t(bt, sVa + (uint32_t)(krow * 128) +
                          (uint32_t)((nchunk ^ (krow & 7)) << 4));
#pragma unroll
                for (int sub = 0; sub < 2; sub++) {
                    const int nf = p * 2 + sub;
                    mma_f16(o[0][nf], a[0], bt[sub * 2], bt[sub * 2 + 1]);
                    mma_f16(o[1][nf], a[1], bt[sub * 2], bt[sub * 2 + 1]);
                }
            }
        }
        // next-iteration top sync protects P/V reuse
    }

    // ---- normalize + write y (fp16) ----
#pragma unroll
    for (int mf = 0; mf < 2; mf++) {
        const int r0 = m0 + mf * 16 + lq;
        const float il0 = 1.0f / stL[r0];
        const float il1 = 1.0f / stL[r0 + 8];
#pragma unroll
        for (int nf = 0; nf < 4; nf++) {
            const int c0 = n0 + nf * 8 + 2 * lr4;
            const size_t ob0 = ((size_t)(b * Tn + qi * 128 + r0)) * Cn + h * 64 + c0;
            const size_t ob1 = ((size_t)(b * Tn + qi * 128 + r0 + 8)) * Cn + h * 64 + c0;
            *(__half2*)&Yg[ob0] =
                __float22half2_rn(make_float2(o[mf][nf][0] * il0, o[mf][nf][1] * il0));
            *(__half2*)&Yg[ob1] =
                __float22half2_rn(make_float2(o[mf][nf][2] * il1, o[mf][nf][3] * il1));
        }
    }
#undef KV_ISSUE
}

// ---------------------------------------------------------------------------
extern "C" void kernel_launch(void* const* d_in, const int* in_sizes, int n_in,
                              void* d_out, int out_size)
{
    const float* x  = (const float*)d_in[0];
    const float* Wq = (const float*)d_in[1];
    const float* Wk = (const float*)d_in[2];
    const float* Wv = (const float*)d_in[3];
    const float* Wo = (const float*)d_in[4];
    float* out = (float*)d_out;

    __half *q, *k, *v, *y, *xh, *wh;
    cudaGetSymbolAddress((void**)&q,  g_q);
    cudaGetSymbolAddress((void**)&k,  g_k);
    cudaGetSymbolAddress((void**)&v,  g_v);
    cudaGetSymbolAddress((void**)&y,  g_y);
    cudaGetSymbolAddress((void**)&xh, g_xh);
    cudaGetSymbolAddress((void**)&wh, g_wh);
    __half* wq_h = wh;
    __half* wk_h = wh + (size_t)Cn * Cn;
    __half* wv_h = wh + (size_t)2 * Cn * Cn;
    __half* wo_h = wh + (size_t)3 * Cn * Cn;

    cudaFuncSetAttribute(gemm_h<true>,  cudaFuncAttributeMaxDynamicSharedMemorySize, GEMM_SMEM_BYTES);
    cudaFuncSetAttribute(gemm_h<false>, cudaFuncAttributeMaxDynamicSharedMemorySize, GEMM_SMEM_BYTES);
    cudaFuncSetAttribute(attn_h, cudaFuncAttributeMaxDynamicSharedMemorySize, ATTN_SMEM_BYTES);

    // 0) convert inputs to fp16
    prep_h<<<dim3(8192, 5), 256>>>(x, Wq, Wk, Wv, Wo);
    // 1) QKV projections + fused RoPE (fp16 in/out)
    gemm_h<true><<<dim3(Cn / 128, Mrows / 128, 3), 256, GEMM_SMEM_BYTES>>>(
        xh, wq_h, wk_h, wv_h, q, k, v, 1);
    // 2) causal flash attention (fp16)
    attn_h<<<dim3(Tn / 128, Hn, Bn), 256, ATTN_SMEM_BYTES>>>(q, k, v, y);
    // 3) output projection (fp16 in, fp32 out)
    gemm_h<false><<<dim3(Cn / 128, Mrows / 128, 1), 256, GEMM_SMEM_BYTES>>>(
        y, wo_h, wo_h, wo_h, out, out, out, 0);
}

// round 16
// speedup vs baseline: 2.3665x; 1.1575x over previous
#include <cuda_runtime.h>
#include <cuda_fp16.h>
#include <math.h>
#include <cstdint>

// Problem constants
#define Bn 2
#define Tn 2048
#define Cn 1024
#define Hn 16
#define Dn 64
#define Mrows (Bn * Tn)   // 4096

// Scratch (allocation-free). fp16 everywhere except final output.
__device__ __half g_q[(size_t)Mrows * Cn];
__device__ __half g_k[(size_t)Mrows * Cn];
__device__ __half g_v[(size_t)Mrows * Cn];
__device__ __half g_y[(size_t)Mrows * Cn];
__device__ __half g_xh[(size_t)Mrows * Cn];       // fp16 x
__device__ __half g_wh[4][(size_t)Cn * Cn];       // fp16 Wq,Wk,Wv,Wo

// ---------------------------------------------------------------------------
// Helpers
// ---------------------------------------------------------------------------
__device__ __forceinline__ uint32_t smem_u32(const void* p) {
    uint32_t a;
    asm("{ .reg .u64 t; cvta.to.shared.u64 t, %1; cvt.u32.u64 %0, t; }" : "=r"(a) : "l"(p));
    return a;
}
__device__ __forceinline__ void cp16(uint32_t dst, const void* src) {
    asm volatile("cp.async.cg.shared.global [%0], [%1], 16;" :: "r"(dst), "l"(src));
}
#define CP_COMMIT() asm volatile("cp.async.commit_group;" ::: "memory")
#define CP_WAIT1()  asm volatile("cp.async.wait_group 1;" ::: "memory")

__device__ __forceinline__ void ldsm_x4(uint32_t* r, uint32_t addr) {
    asm volatile("ldmatrix.sync.aligned.m8n8.x4.shared.b16 {%0,%1,%2,%3}, [%4];"
                 : "=r"(r[0]), "=r"(r[1]), "=r"(r[2]), "=r"(r[3]) : "r"(addr));
}
__device__ __forceinline__ void ldsm_x4_t(uint32_t* r, uint32_t addr) {
    asm volatile("ldmatrix.sync.aligned.m8n8.x4.trans.shared.b16 {%0,%1,%2,%3}, [%4];"
                 : "=r"(r[0]), "=r"(r[1]), "=r"(r[2]), "=r"(r[3]) : "r"(addr));
}

// D(16x8) += A(16x16) * B(16x8), fp16 inputs, fp32 accum
__device__ __forceinline__ void mma_f16(float* d, const uint32_t* a,
                                        uint32_t b0, uint32_t b1) {
    asm volatile(
        "mma.sync.aligned.m16n8k16.row.col.f32.f16.f16.f32 "
        "{%0,%1,%2,%3}, {%4,%5,%6,%7}, {%8,%9}, {%0,%1,%2,%3};"
        : "+f"(d[0]), "+f"(d[1]), "+f"(d[2]), "+f"(d[3])
        : "r"(a[0]), "r"(a[1]), "r"(a[2]), "r"(a[3]), "r"(b0), "r"(b1));
}
// pack two f32 -> one u32 holding half2 (single PTX cvt)
__device__ __forceinline__ uint32_t pack_h2(float x, float y) {
    uint32_t r;
    asm("cvt.rn.f16x2.f32 %0, %1, %2;" : "=r"(r) : "f"(y), "f"(x));
    return r;
}

// ---------------------------------------------------------------------------
// Prep: convert x and weights to fp16
// ---------------------------------------------------------------------------
__global__ void prep_h(const float* __restrict__ x,
                       const float* __restrict__ wq, const float* __restrict__ wk,
                       const float* __restrict__ wv, const float* __restrict__ wo)
{
    const int seg = blockIdx.y;
    const float* src;
    __half* dst;
    int n2;
    if (seg == 0) { src = x; dst = g_xh; n2 = Mrows * Cn / 2; }
    else {
        src = (seg == 1) ? wq : (seg == 2) ? wk : (seg == 3) ? wv : wo;
        dst = g_wh[seg - 1];
        n2 = Cn * Cn / 2;
    }
    const int i = blockIdx.x * blockDim.x + threadIdx.x;
    if (i < n2) {
        float2 v = ((const float2*)src)[i];
        ((__half2*)dst)[i] = __float22half2_rn(v);
    }
}

// ---------------------------------------------------------------------------
// GEMM: C[M,N] = A[M,K] @ W[N,K]^T (fp16 mma.m16n8k16 + ldmatrix, fp32 accum).
// CTA 128x128, BK=64 halfs, 3-stage cp.async, 8 warps (4m x 2n), 32x64 warp tile.
// q output (z==0, rope) is additionally scaled by 0.125 (attention 1/sqrt(d)).
// ---------------------------------------------------------------------------
#define GEMM_SMEM_BYTES 98304   // 2 matrices x 3 stages x 16384 B

template <bool OH>
__global__ __launch_bounds__(256, 2) void gemm_h(
    const __half* __restrict__ A,
    const __half* __restrict__ W0, const __half* __restrict__ W1, const __half* __restrict__ W2,
    void* __restrict__ C0v, void* __restrict__ C1v, void* __restrict__ C2v,
    int do_rope)
{
    extern __shared__ char smc[];
    const uint32_t smbA = smem_u32(smc);
    const uint32_t smbB = smbA + 3 * 16384;

    const int z = blockIdx.z;
    const __half* W = (z == 0) ? W0 : ((z == 1) ? W1 : W2);
    void*        Cv = (z == 0) ? C0v : ((z == 1) ? C1v : C2v);
    const bool rope = (do_rope != 0) && (z < 2);
    const float oscale = (do_rope != 0 && z == 0) ? 0.125f : 1.0f;

    const int tid = threadIdx.x;
    const int wid = tid >> 5, lane = tid & 31;
    const int warpM = wid >> 1, warpN = wid & 1;
    const int lq = lane >> 2, lr4 = lane & 3;
    const int rowBase = blockIdx.y * 128;
    const int colBase = blockIdx.x * 128;

    const int cr = tid >> 1, hlf = tid & 1;
    const __half* Ag = A + (size_t)(rowBase + cr) * Cn + hlf * 32;
    const __half* Wg = W + (size_t)(colBase + cr) * Cn + hlf * 32;
    uint32_t dOf[4];
#pragma unroll
    for (int i = 0; i < 4; i++) {
        const int chunk = hlf * 4 + i;
        dOf[i] = (uint32_t)(cr * 128 + ((chunk ^ (cr & 7)) << 4));
    }

#define G_ISSUE(t, s) do {                                            \
        const __half* _ga = Ag + (t) * 64;                            \
        const __half* _gw = Wg + (t) * 64;                            \
        const uint32_t _ba = smbA + (s) * 16384;                      \
        const uint32_t _bb = smbB + (s) * 16384;                      \
        _Pragma("unroll")                                             \
        for (int _i = 0; _i < 4; _i++) {                              \
            cp16(_ba + dOf[_i], _ga + _i * 8);                        \
            cp16(_bb + dOf[_i], _gw + _i * 8);                        \
        }                                                             \
    } while (0)

    G_ISSUE(0, 0); CP_COMMIT();
    G_ISSUE(1, 1); CP_COMMIT();

    const int lane15 = lane & 15;
    const int aBit = lane >> 4;
    const int bBit = (lane >> 3) & 1;
    uint32_t aOff[2]; int aSwz[2];
#pragma unroll
    for (int mf = 0; mf < 2; mf++) {
        const int r = warpM * 32 + mf * 16 + lane15;
        aOff[mf] = (uint32_t)(r * 128);
        aSwz[mf] = r & 7;
    }
    uint32_t bOff[4]; int bSwz[4];
#pragma unroll
    for (int p = 0; p < 4; p++) {
        const int n = warpN * 64 + p * 16 + ((lane >> 4) << 3) + (lane & 7);
        bOff[p] = (uint32_t)(n * 128);
        bSwz[p] = n & 7;
    }

    float acc[2][8][4];
#pragma unroll
    for (int i = 0; i < 2; i++)
#pragma unroll
        for (int j = 0; j < 8; j++)
#pragma unroll
            for (int k = 0; k < 4; k++) acc[i][j][k] = 0.f;

#pragma unroll 1
    for (int t = 0; t < 16; t++) {
        CP_WAIT1();
        __syncthreads();
        if (t + 2 < 16) G_ISSUE(t + 2, (t + 2) % 3);
        CP_COMMIT();

        const uint32_t sAa = smbA + (t % 3) * 16384;
        const uint32_t sBa = smbB + (t % 3) * 16384;
#pragma unroll
        for (int ks = 0; ks < 4; ks++) {
            uint32_t a[2][4], bf[4][4];
#pragma unroll
            for (int mf = 0; mf < 2; mf++)
                ldsm_x4(a[mf], sAa + aOff[mf] +
                        (uint32_t)(((ks * 2 + aBit) ^ aSwz[mf]) << 4));
#pragma unroll
            for (int p = 0; p < 4; p++)
                ldsm_x4(bf[p], sBa + bOff[p] +
                        (uint32_t)(((ks * 2 + bBit) ^ bSwz[p]) << 4));
#pragma unroll
            for (int nf = 0; nf < 8; nf++) {
                const uint32_t b0 = bf[nf >> 1][(nf & 1) * 2];
                const uint32_t b1 = bf[nf >> 1][(nf & 1) * 2 + 1];
                mma_f16(acc[0][nf], a[0], b0, b1);
                mma_f16(acc[1][nf], a[1], b0, b1);
            }
        }
    }

    // Epilogue
    const float KLOG = 13.287712379549449f / 32.0f;   // log2(10000)/32
#pragma unroll
    for (int mf = 0; mf < 2; mf++) {
        const int r0 = rowBase + warpM * 32 + mf * 16 + lq;
        if (OH) {
            __half* Cm = (__half*)Cv;
            if (!rope) {
#pragma unroll
                for (int nf = 0; nf < 8; nf++) {
                    const int c0 = colBase + warpN * 64 + nf * 8 + 2 * lr4;
                    *(__half2*)&Cm[(size_t)r0 * Cn + c0] =
                        __float22half2_rn(make_float2(acc[mf][nf][0], acc[mf][nf][1]));
                    *(__half2*)&Cm[(size_t)(r0 + 8) * Cn + c0] =
                        __float22half2_rn(make_float2(acc[mf][nf][2], acc[mf][nf][3]));
                }
            } else {
                const int t0 = r0 & (Tn - 1), t1 = (r0 + 8) & (Tn - 1);
#pragma unroll
                for (int nf = 0; nf < 4; nf++) {   // d in [0,32): partner frag nf+4
                    const int dlo = nf * 8 + 2 * lr4;
                    const int c0 = colBase + warpN * 64 + dlo;
#pragma unroll
                    for (int e = 0; e < 2; e++) {
                        const float freq = exp2f(-(float)(dlo + e) * KLOG);
                        float s0, cth0, s1, cth1;
                        sincosf((float)t0 * freq, &s0, &cth0);
                        sincosf((float)t1 * freq, &s1, &cth1);
                        const float lo0 = acc[mf][nf][e],     hi0 = acc[mf][nf + 4][e];
                        const float lo1 = acc[mf][nf][e + 2], hi1 = acc[mf][nf + 4][e + 2];
                        Cm[(size_t)r0 * Cn + c0 + e] =
                            __float2half_rn((lo0 * cth0 - hi0 * s0) * oscale);
                        Cm[(size_t)r0 * Cn + c0 + e + 32] =
                            __float2half_rn((hi0 * cth0 + lo0 * s0) * oscale);
                        Cm[(size_t)(r0 + 8) * Cn + c0 + e] =
                            __float2half_rn((lo1 * cth1 - hi1 * s1) * oscale);
                        Cm[(size_t)(r0 + 8) * Cn + c0 + e + 32] =
                            __float2half_rn((hi1 * cth1 + lo1 * s1) * oscale);
                    }
                }
            }
        } else {
            float* Cm = (float*)Cv;
#pragma unroll
            for (int nf = 0; nf < 8; nf++) {
                const int c0 = colBase + warpN * 64 + nf * 8 + 2 * lr4;
                *(float2*)&Cm[(size_t)r0 * Cn + c0] =
                    make_float2(acc[mf][nf][0], acc[mf][nf][1]);
                *(float2*)&Cm[(size_t)(r0 + 8) * Cn + c0] =
                    make_float2(acc[mf][nf][2], acc[mf][nf][3]);
            }
        }
    }
#undef G_ISSUE
}

// ---------------------------------------------------------------------------
// Flash attention FA2-style: warps partition M only (8 warps x 16 rows),
// S and P stay in registers, softmax via quad shfl, 1 barrier per k-tile.
// q-tile=128, k-tile=64, 3-stage cp.async K/V. Q pre-scaled by 1/8.
// Smem bytes: Q 16384 | K 3x8192 | V 3x8192 = 65536.
// ---------------------------------------------------------------------------
#define QB 0
#define KB 16384
#define VB 40960
#define ATTN_SMEM_BYTES 65536

__global__ __launch_bounds__(256, 2) void attn_h(
    const __half* __restrict__ Qg, const __half* __restrict__ Kg,
    const __half* __restrict__ Vg, __half* __restrict__ Yg)
{
    extern __shared__ char smc[];
    const uint32_t smb = smem_u32(smc);

    const int qi = (int)(gridDim.x - 1 - blockIdx.x);   // long tiles first
    const int h = blockIdx.y, b = blockIdx.z;
    const int tid = threadIdx.x;
    const int wid = tid >> 5, lane = tid & 31;
    const int lq = lane >> 2, lr4 = lane & 3;
    const int m0 = wid * 16;                            // warp row base (16 rows)

    // cp.async mappings
    const int qr = tid >> 1, qci = tid & 1;             // Q: 128 rows, 2 thr/row
    const __half* Qp = Qg + (size_t)(b * Tn + qi * 128 + qr) * Cn + h * 64 + qci * 32;
    const int kr = tid >> 2, kci = tid & 3;             // K/V: 64 rows, 4 thr/row
    const __half* Kp = Kg + (size_t)(b * Tn + kr) * Cn + h * 64 + kci * 16;
    const __half* Vp = Vg + (size_t)(b * Tn + kr) * Cn + h * 64 + kci * 16;
    uint32_t kvOf[2];
#pragma unroll
    for (int i = 0; i < 2; i++) {
        const int chunk = kci * 2 + i;
        kvOf[i] = (uint32_t)(kr * 128 + ((chunk ^ (kr & 7)) << 4));
    }

#define KV_ISSUE(j, s) do {                                                     \
        const __half* _kp = Kp + (size_t)((j) * 64) * Cn;                       \
        const __half* _vp = Vp + (size_t)((j) * 64) * Cn;                       \
        const uint32_t _bk = smb + KB + (s) * 8192;                             \
        const uint32_t _bv = smb + VB + (s) * 8192;                             \
        cp16(_bk + kvOf[0], _kp);     cp16(_bk + kvOf[1], _kp + 8);             \
        cp16(_bv + kvOf[0], _vp);     cp16(_bv + kvOf[1], _vp + 8);             \
    } while (0)

    // Prologue: Q + KV(0) in group0; KV(1) group1
#pragma unroll
    for (int i = 0; i < 4; i++) {
        const int chunk = qci * 4 + i;
        cp16(smb + QB + (uint32_t)(qr * 128 + ((chunk ^ (qr & 7)) << 4)), Qp + i * 8);
    }
    KV_ISSUE(0, 0); CP_COMMIT();
    KV_ISSUE(1, 1); CP_COMMIT();

    // ldmatrix address components
    const int lane15 = lane & 15;
    const int aBit = lane >> 4;
    const int bBit = (lane >> 3) & 1;
    const int qrow = m0 + lane15;
    const uint32_t qOff = (uint32_t)(qrow * 128);
    const int qSwz = qrow & 7;
    uint32_t kOff[4]; int kSwz[4];
#pragma unroll
    for (int p = 0; p < 4; p++) {
        const int n = p * 16 + ((lane >> 4) << 3) + (lane & 7);
        kOff[p] = (uint32_t)(n * 128);
        kSwz[p] = n & 7;
    }
    const int vkl = ((lane >> 3) & 1) * 8 + (lane & 7);   // V trans k-row within 16
    const int vch = lane >> 4;                            // V trans chunk parity

    // Register state: O accum, row stats (rows m0+lq and m0+lq+8)
    float o[8][4];
#pragma unroll
    for (int j = 0; j < 8; j++)
#pragma unroll
        for (int k = 0; k < 4; k++) o[j][k] = 0.f;
    float mOld0 = -1e30f, mOld1 = -1e30f, l0 = 0.f, l1 = 0.f;

    const int jmax = 2 * qi + 2;
#pragma unroll 1
    for (int j = 0; j < jmax; j++) {
        CP_WAIT1();
        __syncthreads();
        if (j + 2 < jmax) KV_ISSUE(j + 2, (j + 2) % 3);
        CP_COMMIT();

        const uint32_t sQa = smb + QB;
        const uint32_t sKa = smb + KB + (j % 3) * 8192;
        const uint32_t sVa = smb + VB + (j % 3) * 8192;

        // ---- S = Q K^T : warp stripe 16 x 64, S in registers ----
        float s[8][4];
#pragma unroll
        for (int nf = 0; nf < 8; nf++)
#pragma unroll
            for (int k = 0; k < 4; k++) s[nf][k] = 0.f;
#pragma unroll
        for (int ks = 0; ks < 4; ks++) {
            uint32_t a[4], bf[4][4];
            ldsm_x4(a, sQa + qOff + (uint32_t)(((ks * 2 + aBit) ^ qSwz) << 4));
#pragma unroll
            for (int p = 0; p < 4; p++)
                ldsm_x4(bf[p], sKa + kOff[p] +
                        (uint32_t)(((ks * 2 + bBit) ^ kSwz[p]) << 4));
#pragma unroll
            for (int nf = 0; nf < 8; nf++)
                mma_f16(s[nf], a, bf[nf >> 1][(nf & 1) * 2], bf[nf >> 1][(nf & 1) * 2 + 1]);
        }

        // ---- causal mask (diagonal blocks only) ----
        if (j >= 2 * qi) {
            const int mg0 = qi * 128 + m0 + lq, mg1 = mg0 + 8;
            const int cb = j * 64 + 2 * lr4;
#pragma unroll
            for (int nf = 0; nf < 8; nf++) {
                const int cg0 = cb + nf * 8, cg1 = cg0 + 1;
                if (cg0 > mg0) s[nf][0] = -1e30f;
                if (cg1 > mg0) s[nf][1] = -1e30f;
                if (cg0 > mg1) s[nf][2] = -1e30f;
                if (cg1 > mg1) s[nf][3] = -1e30f;
            }
        }

        // ---- online softmax in registers (quad = one row) ----
        float mx0 = -1e30f, mx1 = -1e30f;
#pragma unroll
        for (int nf = 0; nf < 8; nf++) {
            mx0 = fmaxf(mx0, fmaxf(s[nf][0], s[nf][1]));
            mx1 = fmaxf(mx1, fmaxf(s[nf][2], s[nf][3]));
        }
        mx0 = fmaxf(mx0, __shfl_xor_sync(0xffffffffu, mx0, 1));
        mx0 = fmaxf(mx0, __shfl_xor_sync(0xffffffffu, mx0, 2));
        mx1 = fmaxf(mx1, __shfl_xor_sync(0xffffffffu, mx1, 1));
        mx1 = fmaxf(mx1, __shfl_xor_sync(0xffffffffu, mx1, 2));
        const float mN0 = fmaxf(mOld0, mx0);
        const float mN1 = fmaxf(mOld1, mx1);
        const float al0 = __expf(mOld0 - mN0);
        const float al1 = __expf(mOld1 - mN1);
        mOld0 = mN0; mOld1 = mN1;

        uint32_t pk[8][2];
        float sum0 = 0.f, sum1 = 0.f;
#pragma unroll
        for (int nf = 0; nf < 8; nf++) {
            const float p0 = __expf(s[nf][0] - mN0);
            const float p1 = __expf(s[nf][1] - mN0);
            const float p2 = __expf(s[nf][2] - mN1);
            const float p3 = __expf(s[nf][3] - mN1);
            sum0 += p0 + p1; sum1 += p2 + p3;
            pk[nf][0] = pack_h2(p0, p1);
            pk[nf][1] = pack_h2(p2, p3);
        }
        sum0 += __shfl_xor_sync(0xffffffffu, sum0, 1);
        sum0 += __shfl_xor_sync(0xffffffffu, sum0, 2);
        sum1 += __shfl_xor_sync(0xffffffffu, sum1, 1);
        sum1 += __shfl_xor_sync(0xffffffffu, sum1, 2);
        l0 = l0 * al0 + sum0;
        l1 = l1 * al1 + sum1;

#pragma unroll
        for (int nf = 0; nf < 8; nf++) {
            o[nf][0] *= al0; o[nf][1] *= al0;
            o[nf][2] *= al1; o[nf][3] *= al1;
        }

        // ---- O += P V (P fragments from registers; V via ldmatrix.trans) ----
#pragma unroll
        for (int kc = 0; kc < 4; kc++) {
            uint32_t a[4];
            a[0] = pk[2 * kc][0];     a[1] = pk[2 * kc][1];
            a[2] = pk[2 * kc + 1][0]; a[3] = pk[2 * kc + 1][1];
            const int krow = kc * 16 + vkl;
#pragma unroll
            for (int po = 0; po < 4; po++) {
                const int nchunk = po * 2 + vch;
                uint32_t bt[4];
                ldsm_x4_t(bt, sVa + (uint32_t)(krow * 128) +
                          (uint32_t)((nchunk ^ (krow & 7)) << 4));
                mma_f16(o[po * 2 + 0], a, bt[0], bt[1]);
                mma_f16(o[po * 2 + 1], a, bt[2], bt[3]);
            }
        }
    }

    // ---- normalize + write y (fp16) ----
    const float il0 = 1.0f / l0;
    const float il1 = 1.0f / l1;
    const int r0 = m0 + lq;
#pragma unroll
    for (int nf = 0; nf < 8; nf++) {
        const int c0 = nf * 8 + 2 * lr4;
        const size_t ob0 = ((size_t)(b * Tn + qi * 128 + r0)) * Cn + h * 64 + c0;
        const size_t ob1 = ((size_t)(b * Tn + qi * 128 + r0 + 8)) * Cn + h * 64 + c0;
        *(__half2*)&Yg[ob0] =
            __float22half2_rn(make_float2(o[nf][0] * il0, o[nf][1] * il0));
        *(__half2*)&Yg[ob1] =
            __float22half2_rn(make_float2(o[nf][2] * il1, o[nf][3] * il1));
    }
#undef KV_ISSUE
}

// ---------------------------------------------------------------------------
extern "C" void kernel_launch(void* const* d_in, const int* in_sizes, int n_in,
                              void* d_out, int out_size)
{
    const float* x  = (const float*)d_in[0];
    const float* Wq = (const float*)d_in[1];
    const float* Wk = (const float*)d_in[2];
    const float* Wv = (const float*)d_in[3];
    const float* Wo = (const float*)d_in[4];
    float* out = (float*)d_out;

    __half *q, *k, *v, *y, *xh, *wh;
    cudaGetSymbolAddress((void**)&q,  g_q);
    cudaGetSymbolAddress((void**)&k,  g_k);
    cudaGetSymbolAddress((void**)&v,  g_v);
    cudaGetSymbolAddress((void**)&y,  g_y);
    cudaGetSymbolAddress((void**)&xh, g_xh);
    cudaGetSymbolAddress((void**)&wh, g_wh);
    __half* wq_h = wh;
    __half* wk_h = wh + (size_t)Cn * Cn;
    __half* wv_h = wh + (size_t)2 * Cn * Cn;
    __half* wo_h = wh + (size_t)3 * Cn * Cn;

    cudaFuncSetAttribute(gemm_h<true>,  cudaFuncAttributeMaxDynamicSharedMemorySize, GEMM_SMEM_BYTES);
    cudaFuncSetAttribute(gemm_h<false>, cudaFuncAttributeMaxDynamicSharedMemorySize, GEMM_SMEM_BYTES);
    cudaFuncSetAttribute(attn_h, cudaFuncAttributeMaxDynamicSharedMemorySize, ATTN_SMEM_BYTES);

    // 0) convert inputs to fp16
    prep_h<<<dim3(8192, 5), 256>>>(x, Wq, Wk, Wv, Wo);
    // 1) QKV projections + fused RoPE (q scaled by 1/8)
    gemm_h<true><<<dim3(Cn / 128, Mrows / 128, 3), 256, GEMM_SMEM_BYTES>>>(
        xh, wq_h, wk_h, wv_h, q, k, v, 1);
    // 2) causal flash attention (register-resident FA2)
    attn_h<<<dim3(Tn / 128, Hn, Bn), 256, ATTN_SMEM_BYTES>>>(q, k, v, y);
    // 3) output projection (fp16 in, fp32 out)
    gemm_h<false><<<dim3(Cn / 128, Mrows / 128, 1), 256, GEMM_SMEM_BYTES>>>(
        y, wo_h, wo_h, wo_h, out, out, out, 0);
}